// round 3
// baseline (speedup 1.0000x reference)
#include <cuda_runtime.h>

#define HDIM  1024
#define BATCH 256
#define TLEN  512
#define NCTA  128
#define BM    64
#define BN    32
#define BK    32
#define AST   65   // As stride in float2 units (padding for conflict-free smem)

// ---- smem layout (floats): Wsm[32768] | As2(u64)[2*32*65] | xs[64] | red[256] | wout[1024]
#define SMEM_FLOATS (32768 + 2*BK*AST*2 + 64 + 256 + 1024)
#define SMEM_BYTES  (SMEM_FLOATS * 4)

// -------- device scratch --------
__device__ float g_hA[BATCH * HDIM];
__device__ float g_hB[BATCH * HDIM];
__device__ float g_out[BATCH * TLEN];
__device__ float g_feat[BATCH * 3];
__device__ float g_lossnum;
__device__ unsigned g_count;            // monotonic across replays
__device__ volatile unsigned g_release; // monotonic across replays

// -------- f32x2 helpers --------
__device__ __forceinline__ unsigned long long pack2(float lo, float hi) {
    unsigned long long r;
    asm("mov.b64 %0, {%1, %2};" : "=l"(r) : "f"(lo), "f"(hi));
    return r;
}
__device__ __forceinline__ void unpack2(unsigned long long v, float& lo, float& hi) {
    asm("mov.b64 {%0, %1}, %2;" : "=f"(lo), "=f"(hi) : "l"(v));
}
__device__ __forceinline__ void fma2(unsigned long long& acc,
                                     unsigned long long a, unsigned long long b) {
    asm("fma.rn.f32x2 %0, %1, %2, %0;" : "+l"(acc) : "l"(a), "l"(b));
}

// -------- grid barrier: epoch-based, monotonic, replay-safe --------
__device__ __forceinline__ void gsync(unsigned& epoch) {
    __syncthreads();
    if (threadIdx.x == 0) {
        epoch++;
        __threadfence();
        unsigned old = atomicAdd(&g_count, 1u);
        if (old == epoch * NCTA - 1u) {
            __threadfence();
            g_release = epoch;
        } else {
            while (g_release < epoch) { __nanosleep(32); }
            __threadfence();
        }
    }
    __syncthreads();
}

extern "C" __global__ void __launch_bounds__(256, 1) persist_kernel(
    const float* __restrict__ input, const int* __restrict__ seqlen,
    const float* __restrict__ Wih_e, const float* __restrict__ Whh_e,
    const float* __restrict__ bih_e, const float* __restrict__ bhh_e,
    const float* __restrict__ Wenc,  const float* __restrict__ benc,
    const float* __restrict__ Wdec,  const float* __restrict__ bdec,
    const float* __restrict__ Wih_d, const float* __restrict__ Whh_d,
    const float* __restrict__ bih_d, const float* __restrict__ bhh_d,
    const float* __restrict__ Wout,  const float* __restrict__ bout,
    float* __restrict__ dout, int out_size)
{
    extern __shared__ float smem[];
    float* Wsm = smem;                                                  // 1024 x 32
    unsigned long long* As2 = (unsigned long long*)(smem + 32768);      // 2 x 32 x 65
    float* xs      = smem + 32768 + 2 * BK * AST * 2;                   // 64
    float* red     = xs + 64;                                           // 256
    float* wout_sh = red + 256;                                         // 1024

    const int tid = threadIdx.x;
    const int bx  = blockIdx.x;
    const int nt  = bx & 31;        // 32 n-tiles
    const int mt  = bx >> 5;        // 4  m-tiles
    const int nblk = nt * BN;
    const int m0   = mt * BM;
    const int m_local = (tid & 15) | (((tid >> 6) & 3) << 4);  // 0..63
    const int ng      = (tid >> 4) & 3;                        // 0..3
    const float bout0 = bout[0];

    unsigned epoch = g_release;   // stable base from previous replay

    // ---- init: zero h0 (encoder), reset loss ----
    {
        int gtid = bx * 256 + tid;
#pragma unroll
        for (int r = 0; r < 8; r++) g_hA[gtid + r * 32768] = 0.f;
        if (gtid == 0) g_lossnum = 0.f;
    }
    gsync(epoch);

    // ================= two RNN phases =================
    for (int phase = 0; phase < 2; phase++) {
        const float* Whh = phase ? Whh_d : Whh_e;
        const float* Wih = phase ? Wih_d : Wih_e;
        const float* bih = phase ? bih_d : bih_e;
        const float* bhh = phase ? bhh_d : bhh_e;

        // preload this CTA's Whh slice (BN rows x HDIM) into smem, transposed [k][nn]
        for (int i = tid; i < BN * HDIM / 4; i += 256) {
            int nn = i >> 8;       // 0..31
            int kq = i & 255;      // float4 index along k
            float4 v = *(const float4*)(Whh + (nblk + nn) * HDIM + kq * 4);
            Wsm[(kq * 4 + 0) * BN + nn] = v.x;
            Wsm[(kq * 4 + 1) * BN + nn] = v.y;
            Wsm[(kq * 4 + 2) * BN + nn] = v.z;
            Wsm[(kq * 4 + 3) * BN + nn] = v.w;
        }
        if (phase == 1)
            for (int i = tid; i < HDIM; i += 256) wout_sh[i] = Wout[i];

        // per-thread constants for this phase
        const int n0 = nblk + ng * 8;
        unsigned long long wih2[4], bias2[4];
#pragma unroll
        for (int j = 0; j < 4; j++) {
            wih2[j]  = pack2(Wih[n0 + 2 * j], Wih[n0 + 2 * j + 1]);
            bias2[j] = pack2(bih[n0 + 2 * j] + bhh[n0 + 2 * j],
                             bih[n0 + 2 * j + 1] + bhh[n0 + 2 * j + 1]);
        }
        __syncthreads();

        float* h_old = g_hA;
        float* h_new = g_hB;

        for (int t = 0; t < TLEN; t++) {
            // ---- per-row scalar input x ----
            if (phase == 0) {
                if (tid < BM) xs[tid] = input[(m0 + tid) * TLEN + t];
            } else {
                // redundant per-CTA dot(h_old[row,:], Wout)
                int row = tid >> 2, seg = tid & 3;
                const float* hp = h_old + (m0 + row) * HDIM + seg * 256;
                const float* wp = wout_sh + seg * 256;
                float s = 0.f;
#pragma unroll 8
                for (int k = 0; k < 256; k += 4) {
                    float4 hv = *(const float4*)(hp + k);
                    float4 wv = *(const float4*)(wp + k);
                    s = fmaf(hv.x, wv.x, s); s = fmaf(hv.y, wv.y, s);
                    s = fmaf(hv.z, wv.z, s); s = fmaf(hv.w, wv.w, s);
                }
                red[tid] = s;
                __syncthreads();
                if (tid < BM) {
                    float v = red[tid * 4] + red[tid * 4 + 1] +
                              red[tid * 4 + 2] + red[tid * 4 + 3] + bout0;
                    if (t > 0) {
                        xs[tid] = v;
                        if (nt == 0) g_out[(m0 + tid) * TLEN + (t - 1)] = v;
                    } else xs[tid] = 0.f;
                }
            }
            __syncthreads();

            float x = xs[m_local];
            unsigned long long x2 = pack2(x, x);
            unsigned long long acc2[4];
#pragma unroll
            for (int j = 0; j < 4; j++) { acc2[j] = bias2[j]; fma2(acc2[j], x2, wih2[j]); }

            // ---- stream A (h_old rows) through double-buffered smem ----
            float4 areg[2];
#pragma unroll
            for (int r = 0; r < 2; r++) {
                int idx = tid + r * 256, mm = idx >> 3, kq = idx & 7;
                areg[r] = *(const float4*)(h_old + (m0 + mm) * HDIM + kq * 4);
            }
            int buf = 0;
            for (int k0 = 0; k0 < HDIM; k0 += BK) {
                unsigned long long* Ab = As2 + buf * BK * AST;
#pragma unroll
                for (int r = 0; r < 2; r++) {
                    int idx = tid + r * 256, mm = idx >> 3, kq = idx & 7;
                    Ab[(kq * 4 + 0) * AST + mm] = pack2(areg[r].x, areg[r].x);
                    Ab[(kq * 4 + 1) * AST + mm] = pack2(areg[r].y, areg[r].y);
                    Ab[(kq * 4 + 2) * AST + mm] = pack2(areg[r].z, areg[r].z);
                    Ab[(kq * 4 + 3) * AST + mm] = pack2(areg[r].w, areg[r].w);
                }
                __syncthreads();
                if (k0 + BK < HDIM) {
#pragma unroll
                    for (int r = 0; r < 2; r++) {
                        int idx = tid + r * 256, mm = idx >> 3, kq = idx & 7;
                        areg[r] = *(const float4*)(h_old + (m0 + mm) * HDIM + k0 + BK + kq * 4);
                    }
                }
                const float* wp = Wsm + k0 * BN + ng * 8;
#pragma unroll 8
                for (int kk = 0; kk < BK; kk++) {
                    unsigned long long a2 = Ab[kk * AST + m_local];
                    ulonglong2 wa = *(const ulonglong2*)(wp + kk * BN);
                    ulonglong2 wb = *(const ulonglong2*)(wp + kk * BN + 4);
                    fma2(acc2[0], a2, wa.x); fma2(acc2[1], a2, wa.y);
                    fma2(acc2[2], a2, wb.x); fma2(acc2[3], a2, wb.y);
                }
                buf ^= 1;
            }

            // ---- tanh + store ----
            float o[8];
#pragma unroll
            for (int j = 0; j < 4; j++) unpack2(acc2[j], o[2 * j], o[2 * j + 1]);
            float4 r0 = make_float4(tanhf(o[0]), tanhf(o[1]), tanhf(o[2]), tanhf(o[3]));
            float4 r1 = make_float4(tanhf(o[4]), tanhf(o[5]), tanhf(o[6]), tanhf(o[7]));
            float* hw = h_new + (m0 + m_local) * HDIM + n0;
            *(float4*)(hw) = r0;
            *(float4*)(hw + 4) = r1;

            gsync(epoch);
            float* tmp = h_old; h_old = h_new; h_new = tmp;
        } // t  (final h is in g_hA: 512 swaps)

        if (phase == 0) {
            // ---- features = sigmoid(hT @ Wenc^T + benc) ----
            int wid = tid >> 5, lane = tid & 31;
            if (wid < 6) {
                int d = bx * 6 + wid;              // 0..767
                int b = d / 3, e = d - b * 3;
                const float* hp = g_hA + b * HDIM;
                const float* wp = Wenc + e * HDIM;
                float s = 0.f;
                for (int k = lane * 4; k < HDIM; k += 128) {
                    float4 hv = *(const float4*)(hp + k);
                    float4 wv = *(const float4*)(wp + k);
                    s = fmaf(hv.x, wv.x, s); s = fmaf(hv.y, wv.y, s);
                    s = fmaf(hv.z, wv.z, s); s = fmaf(hv.w, wv.w, s);
                }
#pragma unroll
                for (int o = 16; o; o >>= 1) s += __shfl_xor_sync(0xffffffff, s, o);
                if (lane == 0) g_feat[b * 3 + e] = 1.f / (1.f + expf(-(s + benc[e])));
            }
            gsync(epoch);
            // ---- h0 = features @ Wdec^T + bdec into g_hA ----
#pragma unroll
            for (int r = 0; r < 8; r++) {
                int i = bx * 2048 + r * 256 + tid;
                int b = i >> 10, j = i & 1023;
                g_hA[i] = bdec[j] + g_feat[b * 3] * Wdec[j * 3]
                                  + g_feat[b * 3 + 1] * Wdec[j * 3 + 1]
                                  + g_feat[b * 3 + 2] * Wdec[j * 3 + 2];
            }
            gsync(epoch);
        }
    } // phases

    // ---- tail: out[:, T-1] = dot(h_T, Wout) + bout (2 rows per CTA) ----
    {
        int half = tid >> 7, l = tid & 127;
        int b = bx * 2 + half;
        const float* hp = g_hA + b * HDIM;
        float s = 0.f;
        for (int k = l * 4; k < HDIM; k += 512) {
            float4 hv = *(const float4*)(hp + k);
            float4 wv = *(const float4*)(Wout + k);
            s = fmaf(hv.x, wv.x, s); s = fmaf(hv.y, wv.y, s);
            s = fmaf(hv.z, wv.z, s); s = fmaf(hv.w, wv.w, s);
        }
#pragma unroll
        for (int o = 16; o; o >>= 1) s += __shfl_xor_sync(0xffffffff, s, o);
        if ((tid & 31) == 0) red[tid >> 5] = s;
        __syncthreads();
        if (tid == 0) {
            g_out[(bx * 2) * TLEN + TLEN - 1]     = red[0] + red[1] + red[2] + red[3] + bout0;
            g_out[(bx * 2 + 1) * TLEN + TLEN - 1] = red[4] + red[5] + red[6] + red[7] + bout0;
        }
        __syncthreads();
    }

    // ---- masked MSE numerator (2 rows per CTA, same rows as tail) ----
    {
        int half = tid >> 7, l = tid & 127;
        int b = bx * 2 + half;
        int L = seqlen[b];
        float s = 0.f;
        for (int t = l; t < L; t += 128) {
            float d = input[b * TLEN + t] - g_out[b * TLEN + t];
            s = fmaf(d, d, s);
        }
#pragma unroll
        for (int o = 16; o; o >>= 1) s += __shfl_xor_sync(0xffffffff, s, o);
        if ((tid & 31) == 0) red[tid >> 5] = s;
        __syncthreads();
        if (tid == 0)
            atomicAdd(&g_lossnum, red[0] + red[1] + red[2] + red[3] +
                                  red[4] + red[5] + red[6] + red[7]);
        __syncthreads();
    }
    gsync(epoch);

    // ---- finalize loss (CTA 0) ----
    if (bx == 0) {
        red[tid] = (float)seqlen[tid];   // BATCH == 256 == blockDim
        __syncthreads();
        for (int o = 128; o; o >>= 1) {
            if (tid < o) red[tid] += red[tid + o];
            __syncthreads();
        }
        if (tid == 0 && out_size > 0) dout[0] = g_lossnum / red[0];
    }

    // ---- pack (loss, input, output, features) into dout ----
    {
        int chunk = (out_size + NCTA - 1) / NCTA;
        int lo = bx * chunk;
        int hi = lo + chunk; if (hi > out_size) hi = out_size;
        for (int i = lo + tid; i < hi; i += 256) {
            if (i == 0) continue;
            int j = i - 1;
            if (j < BATCH * TLEN) { dout[i] = input[j]; continue; }
            j -= BATCH * TLEN;
            if (j < BATCH * TLEN) { dout[i] = g_out[j]; continue; }
            j -= BATCH * TLEN;
            if (j < BATCH * 3) { dout[i] = g_feat[j]; continue; }
            dout[i] = 0.f;
        }
    }
}

extern "C" void kernel_launch(void* const* d_in, const int* in_sizes, int n_in,
                              void* d_out, int out_size) {
    const float* input  = (const float*)d_in[0];
    const int*   seqlen = (const int*)d_in[1];
    const float* Wih_e = (const float*)d_in[2];
    const float* Whh_e = (const float*)d_in[3];
    const float* bih_e = (const float*)d_in[4];
    const float* bhh_e = (const float*)d_in[5];
    const float* Wenc  = (const float*)d_in[6];
    const float* benc  = (const float*)d_in[7];
    const float* Wdec  = (const float*)d_in[8];
    const float* bdec  = (const float*)d_in[9];
    const float* Wih_d = (const float*)d_in[10];
    const float* Whh_d = (const float*)d_in[11];
    const float* bih_d = (const float*)d_in[12];
    const float* bhh_d = (const float*)d_in[13];
    const float* Wout  = (const float*)d_in[14];
    const float* bout  = (const float*)d_in[15];

    cudaFuncSetAttribute(persist_kernel,
                         cudaFuncAttributeMaxDynamicSharedMemorySize, SMEM_BYTES);
    persist_kernel<<<NCTA, 256, SMEM_BYTES>>>(
        input, seqlen, Wih_e, Whh_e, bih_e, bhh_e, Wenc, benc,
        Wdec, bdec, Wih_d, Whh_d, bih_d, bhh_d, Wout, bout,
        (float*)d_out, out_size);
}